// round 8
// baseline (speedup 1.0000x reference)
#include <cuda_runtime.h>
#include <stdint.h>

#define Bb   64
#define Tt   128
#define Ee   256
#define Hh   512
#define G4H  2048
#define GSZ  (Tt*Bb*G4H)   /* 16,777,216 floats per gate buffer */
#define PADM 132           /* padded m/n stride for ff tf32 smem tiles */
#define GST  34            /* padded stride of gate-tile smem */

typedef unsigned long long u64;

// ---------------- scratch (__device__ globals: allocation-free) ----------------
__device__ float  g_x0[Tt*Bb*Ee];                // embedded inputs  [T*B, E]
__device__ float  g_x1[Tt*Bb*2*Hh];              // layer-0 outputs  [T*B, 2H]
__device__ float  g_G[(size_t)4*GSZ];            // gate pre-acts: G0f,G0b,G1f,G1b
__device__ float2 g_WP[4][256*2048];             // Whh tf32 pairs: [kb*4+tig][j]=(W[j][k],W[j][k+4])
__device__ float2 g_hP[4][512*32];               // h tf32 pairs: [k][i]=(h[k][m],h[k][m+8]), i=(m/16)*8+(m%8)
__device__ float  g_hT[4][Hh*Bb];                // final h [k][b] per sequence (logits only)
__device__ float  g_c[4][Bb*Hh];                 // c state per sequence
__device__ unsigned g_bar[2][2];                 // [layer][dir] barrier counters

// ---------------- helpers ----------------
__device__ __forceinline__ float sigm(float x) { return 1.f / (1.f + __expf(-x)); }
__device__ __forceinline__ uint32_t f2tf32(float x) {
    uint32_t r; asm("cvt.rna.tf32.f32 %0, %1;" : "=r"(r) : "f"(x)); return r;
}
__device__ __forceinline__ uint32_t fu(float x) { return __float_as_uint(x); }
__device__ __forceinline__ void mma_tf32(float* c,
        uint32_t a0, uint32_t a1, uint32_t a2, uint32_t a3,
        uint32_t b0, uint32_t b1) {
    asm volatile("mma.sync.aligned.m16n8k8.row.col.f32.tf32.tf32.f32 "
        "{%0,%1,%2,%3}, {%4,%5,%6,%7}, {%8,%9}, {%0,%1,%2,%3};"
        : "+f"(c[0]), "+f"(c[1]), "+f"(c[2]), "+f"(c[3])
        : "r"(a0), "r"(a1), "r"(a2), "r"(a3), "r"(b0), "r"(b1));
}

// ---------------- init: zero hP, c, barriers ----------------
__global__ void init_states() {
    int i = blockIdx.x * blockDim.x + threadIdx.x;
    if (i < 4*512*32*2) ((float*)g_hP)[i] = 0.f;
    if (i < 4*Bb*Hh)    ((float*)g_c)[i] = 0.f;
    if (i < 4)          ((unsigned*)g_bar)[i] = 0u;
}

// ---------------- Whh -> paired tf32 WP ----------------
__global__ void transposeWP(const float* __restrict__ W, int seq) {
    __shared__ float tile[32][33];
    int j0 = blockIdx.x * 32, k0 = blockIdx.y * 32;
    int tx = threadIdx.x, ty = threadIdx.y;
#pragma unroll
    for (int r = 0; r < 32; r += 8)
        tile[ty + r][tx] = W[(size_t)(j0 + ty + r) * Hh + k0 + tx];
    __syncthreads();
    float2* WP = g_WP[seq];
#pragma unroll
    for (int r = 0; r < 32; r += 8) {
        int kl = ty + r;
        if ((kl & 7) < 4) {
            int k = k0 + kl;
            float v1 = tile[tx][kl];
            float v2 = tile[tx][kl + 4];
            int p = ((k >> 3) << 2) + (k & 3);
            WP[(size_t)p * 2048 + j0 + tx] =
                make_float2(__uint_as_float(f2tf32(v1)), __uint_as_float(f2tf32(v2)));
        }
    }
}

// ---------------- embedding gather ----------------
__global__ void gather_embed(const int* __restrict__ q, const float* __restrict__ emb) {
    int r = blockIdx.x;              // r = t*B + b
    int b = r & (Bb - 1);
    int t = r >> 6;
    int qi = q[b * Tt + t];
    const float4* src = (const float4*)(emb + (size_t)qi * Ee);
    float4* dst = (float4*)(g_x0 + (size_t)r * Ee);
    dst[threadIdx.x] = src[threadIdx.x];
}

// ---------------- feedforward GEMM via tf32 mma (unchanged from R7) ----------------
__global__ __launch_bounds__(256) void sgemm_tf32(int asel, int gsel, int K,
        const float* __restrict__ W,
        const float* __restrict__ b1, const float* __restrict__ b2)
{
    const float* __restrict__ A = asel ? g_x1 : g_x0;
    float* __restrict__ C = g_G + (size_t)gsel * GSZ;

    __shared__ uint32_t As[2][16*PADM];
    __shared__ uint32_t Bs[2][16*PADM];

    const int tid = threadIdx.x;
    const int m0 = blockIdx.y * 128, n0 = blockIdx.x * 128;
    const int w = tid >> 5, lane = tid & 31;
    const int gid = lane >> 2, tig = lane & 3;
    const int wm = (w & 1) * 64;
    const int wn = (w >> 1) * 32;

    float acc[4][4][4];
#pragma unroll
    for (int mt = 0; mt < 4; mt++)
#pragma unroll
        for (int nt = 0; nt < 4; nt++)
#pragma unroll
            for (int i = 0; i < 4; i++) acc[mt][nt][i] = 0.f;

    const int sr = tid >> 2;
    const int sc = (tid & 3) * 4;
    const float* Ar0 = A + (size_t)(m0 + sr) * K + sc;
    const float* Ar1 = A + (size_t)(m0 + sr + 64) * K + sc;
    const float* Wr0 = W + (size_t)(n0 + sr) * K + sc;
    const float* Wr1 = W + (size_t)(n0 + sr + 64) * K + sc;

#define STS_T(bsel, va0, va1, vb0, vb1) { \
    As[bsel][(sc+0)*PADM + sr]    = f2tf32(va0.x); \
    As[bsel][(sc+1)*PADM + sr]    = f2tf32(va0.y); \
    As[bsel][(sc+2)*PADM + sr]    = f2tf32(va0.z); \
    As[bsel][(sc+3)*PADM + sr]    = f2tf32(va0.w); \
    As[bsel][(sc+0)*PADM + sr+64] = f2tf32(va1.x); \
    As[bsel][(sc+1)*PADM + sr+64] = f2tf32(va1.y); \
    As[bsel][(sc+2)*PADM + sr+64] = f2tf32(va1.z); \
    As[bsel][(sc+3)*PADM + sr+64] = f2tf32(va1.w); \
    Bs[bsel][(sc+0)*PADM + sr]    = f2tf32(vb0.x); \
    Bs[bsel][(sc+1)*PADM + sr]    = f2tf32(vb0.y); \
    Bs[bsel][(sc+2)*PADM + sr]    = f2tf32(vb0.z); \
    Bs[bsel][(sc+3)*PADM + sr]    = f2tf32(vb0.w); \
    Bs[bsel][(sc+0)*PADM + sr+64] = f2tf32(vb1.x); \
    Bs[bsel][(sc+1)*PADM + sr+64] = f2tf32(vb1.y); \
    Bs[bsel][(sc+2)*PADM + sr+64] = f2tf32(vb1.z); \
    Bs[bsel][(sc+3)*PADM + sr+64] = f2tf32(vb1.w); }

    {
        float4 va0 = *(const float4*)Ar0;
        float4 va1 = *(const float4*)Ar1;
        float4 vb0 = *(const float4*)Wr0;
        float4 vb1 = *(const float4*)Wr1;
        STS_T(0, va0, va1, vb0, vb1);
    }
    __syncthreads();

    int buf = 0;
    for (int kt = 0; kt < K; kt += 16) {
        float4 va0, va1, vb0, vb1;
        bool more = (kt + 16 < K);
        if (more) {
            va0 = *(const float4*)(Ar0 + kt + 16);
            va1 = *(const float4*)(Ar1 + kt + 16);
            vb0 = *(const float4*)(Wr0 + kt + 16);
            vb1 = *(const float4*)(Wr1 + kt + 16);
        }
#pragma unroll
        for (int kk = 0; kk < 16; kk += 8) {
            uint32_t af[4][4], bf[4][2];
            const uint32_t* a_lo = &As[buf][(kk + tig) * PADM + wm + gid];
            const uint32_t* a_hi = &As[buf][(kk + tig + 4) * PADM + wm + gid];
            const uint32_t* b_lo = &Bs[buf][(kk + tig) * PADM + wn + gid];
            const uint32_t* b_hi = &Bs[buf][(kk + tig + 4) * PADM + wn + gid];
#pragma unroll
            for (int mt = 0; mt < 4; mt++) {
                af[mt][0] = a_lo[mt*16];
                af[mt][1] = a_lo[mt*16 + 8];
                af[mt][2] = a_hi[mt*16];
                af[mt][3] = a_hi[mt*16 + 8];
            }
#pragma unroll
            for (int nt = 0; nt < 4; nt++) {
                bf[nt][0] = b_lo[nt*8];
                bf[nt][1] = b_hi[nt*8];
            }
#pragma unroll
            for (int mt = 0; mt < 4; mt++)
#pragma unroll
                for (int nt = 0; nt < 4; nt++)
                    mma_tf32(acc[mt][nt], af[mt][0], af[mt][1], af[mt][2], af[mt][3],
                             bf[nt][0], bf[nt][1]);
        }
        if (more) {
            STS_T(buf ^ 1, va0, va1, vb0, vb1);
            __syncthreads();
            buf ^= 1;
        }
    }
#undef STS_T

#pragma unroll
    for (int nt = 0; nt < 4; nt++) {
        int gn = n0 + wn + nt * 8 + 2 * tig;
        float bs0 = b1[gn]   + b2[gn];
        float bs1 = b1[gn+1] + b2[gn+1];
#pragma unroll
        for (int mt = 0; mt < 4; mt++) {
            int gm = m0 + wm + mt * 16 + gid;
            float* c0 = C + (size_t)gm * G4H + gn;
            float* c1 = C + (size_t)(gm + 8) * G4H + gn;
            c0[0] = acc[mt][nt][0] + bs0;
            c0[1] = acc[mt][nt][1] + bs1;
            c1[0] = acc[mt][nt][2] + bs0;
            c1[1] = acc[mt][nt][3] + bs1;
        }
    }
}

// ---------------- per-direction software barrier (release/acquire) ----------------
__device__ __forceinline__ void dirbar(unsigned* ctr, unsigned target) {
    __syncthreads();
    if (threadIdx.x == 0) {
        asm volatile("red.release.gpu.global.add.u32 [%0], %1;"
                     :: "l"(ctr), "r"(1u) : "memory");
        unsigned v;
        do {
            asm volatile("ld.acquire.gpu.global.u32 %0, [%1];"
                         : "=r"(v) : "l"(ctr) : "memory");
            if (v >= target) break;
            __nanosleep(32);
        } while (true);
    }
    __syncthreads();
}

// ---------------- persistent recurrence: tf32 mma, one layer, both dirs ----------------
// 128 blocks x 256 thr. dir=blk>>6, sub=blk&63 -> 8 h-cols. Warp w: gate g=w&3,
// m-half (w>>2)*32, full K=512: 2 x m16n8k8 mma per k8. A from hP (tf32 pairs, L2),
// B from WP (tf32 pairs, L1-resident). Gate tile exchanged via 8.7KB smem, fused
// LSTM elementwise, ONE global barrier per step.
__global__ __launch_bounds__(256, 1) void lstm_persist(int layer)
{
    __shared__ float gs[Bb * GST];               // 8704 B

    const int tid = threadIdx.x;
    const int dir = blockIdx.x >> 6;
    const int sub = blockIdx.x & 63;
    const int seq = layer * 2 + dir;
    const int w    = tid >> 5;
    const int lane = tid & 31;
    const int gid  = lane >> 2;                  // 0..7
    const int tig  = lane & 3;                   // 0..3
    const int g    = w & 3;                      // gate
    const int m0w  = (w >> 2) * 32;              // m half
    const int base = (w >> 2) * 16;              // hP i-base for this m half

    const float2* __restrict__ WP = g_WP[seq];
    const float2* __restrict__ hP = g_hP[seq];
    float* __restrict__ hPf = (float*)g_hP[seq];
    float* __restrict__ hT  = g_hT[seq];
    float* __restrict__ cs  = g_c[seq];
    const float* __restrict__ Gseq = g_G + (size_t)seq * GSZ;
    unsigned* bar = &g_bar[layer][dir];

    const int jn = g * Hh + sub * 8 + gid;       // B column
    const float2* Bp  = WP + (size_t)tig * 2048 + jn;            // + kb*4*2048
    const float2* Ap0 = hP + tig * 32 + base + gid;              // k = kb*8+tig
    const float2* Ap1 = hP + (tig + 4) * 32 + base + gid;        // k = kb*8+tig+4

    const int ew_m = tid >> 3, ew_u = tid & 7;
    const int gcw = g * 8 + 2 * tig;             // smem gate col for epilogue

    for (int s = 0; s < Tt; s++) {
        const int t = dir ? (Tt - 1 - s) : s;

        // ---------- prefetch gate pre-acts (DRAM) ----------
        const float* Gt = Gseq + (size_t)t * Bb * G4H;
        float gpre[2][4];
#pragma unroll
        for (int e = 0; e < 2; e++)
#pragma unroll
            for (int gg = 0; gg < 4; gg++)
                gpre[e][gg] = __ldcg(&Gt[(size_t)(ew_m + e*32) * G4H + gg * Hh + sub * 8 + ew_u]);

        // ---------- tensor-core GEMM: warp m32n8, K=512 ----------
        float acc0[4] = {0.f, 0.f, 0.f, 0.f};
        float acc1[4] = {0.f, 0.f, 0.f, 0.f};
#pragma unroll 4
        for (int kb = 0; kb < 64; kb++) {
            float2 bv  = Bp[(size_t)kb * 4 * 2048];
            float2 a00 = __ldcg(Ap0 + kb * 256);
            float2 a01 = __ldcg(Ap1 + kb * 256);
            float2 a10 = __ldcg(Ap0 + kb * 256 + 8);
            float2 a11 = __ldcg(Ap1 + kb * 256 + 8);
            mma_tf32(acc0, fu(a00.x), fu(a00.y), fu(a01.x), fu(a01.y), fu(bv.x), fu(bv.y));
            mma_tf32(acc1, fu(a10.x), fu(a10.y), fu(a11.x), fu(a11.y), fu(bv.x), fu(bv.y));
        }

        // ---------- exchange gate tile via smem ----------
        *(float2*)&gs[(m0w + gid)      * GST + gcw] = make_float2(acc0[0], acc0[1]);
        *(float2*)&gs[(m0w + gid + 8)  * GST + gcw] = make_float2(acc0[2], acc0[3]);
        *(float2*)&gs[(m0w + 16 + gid) * GST + gcw] = make_float2(acc1[0], acc1[1]);
        *(float2*)&gs[(m0w + 24 + gid) * GST + gcw] = make_float2(acc1[2], acc1[3]);
        __syncthreads();

        // ---------- fused LSTM elementwise ----------
#pragma unroll
        for (int e = 0; e < 2; e++) {
            int m = ew_m + e * 32;
            float pre[4];
#pragma unroll
            for (int gg = 0; gg < 4; gg++)
                pre[gg] = gpre[e][gg] + gs[m * GST + gg * 8 + ew_u];
            float i_s = sigm(pre[0]);
            float f_s = sigm(pre[1]);
            float g_t = tanhf(pre[2]);
            float o_s = sigm(pre[3]);
            int ci = m * Hh + sub * 8 + ew_u;
            float cn = f_s * cs[ci] + i_s * g_t;
            float hn = o_s * tanhf(cn);
            cs[ci] = cn;
            // h -> tf32 pair buffer for next step's A operand
            int k = sub * 8 + ew_u;
            int ip = ((m >> 4) << 3) + (m & 7);
            hPf[((size_t)k * 32 + ip) * 2 + ((m >> 3) & 1)] = __uint_as_float(f2tf32(hn));
            if (layer == 0)
                g_x1[((size_t)t * Bb + m) * (2*Hh) + dir * Hh + sub * 8 + ew_u] = hn;
            if (s == Tt - 1)
                hT[k * Bb + m] = hn;             // final hidden, logits only
        }

        dirbar(bar, 64u * (s + 1));
    }
}

// ---------------- output head: logits + log_softmax ----------------
__global__ void logits_kernel(const float* __restrict__ Wout,
                              const float* __restrict__ bout,
                              float* __restrict__ out)
{
    __shared__ float h[2048];
    __shared__ float red[256];
    __shared__ float lg[32];
    int b = blockIdx.x, tid = threadIdx.x;
    for (int i = tid; i < 2048; i += 256) {
        int seg = i >> 9, k = i & 511;           // order: l0f, l0b, l1f, l1b
        h[i] = g_hT[seg][k * Bb + b];
    }
    __syncthreads();
    int e = tid >> 3, part = tid & 7;
    const float4* wrow = (const float4*)(Wout + (size_t)e * 2048 + part * 256);
    const float4* hp   = (const float4*)(h + part * 256);
    float sum = 0.f;
#pragma unroll 8
    for (int i = 0; i < 64; i++) {
        float4 wv = wrow[i], hv = hp[i];
        sum += wv.x*hv.x + wv.y*hv.y + wv.z*hv.z + wv.w*hv.w;
    }
    red[tid] = sum;
    __syncthreads();
    if (part == 0) {
        float sacc = 0.f;
#pragma unroll
        for (int i = 0; i < 8; i++) sacc += red[tid + i];
        lg[e] = sacc + bout[e];
    }
    __syncthreads();
    if (tid < 32) {
        float v = lg[tid];
        float mx = v;
#pragma unroll
        for (int off = 16; off > 0; off >>= 1)
            mx = fmaxf(mx, __shfl_xor_sync(0xffffffffu, mx, off));
        float ex = __expf(v - mx);
        float se = ex;
#pragma unroll
        for (int off = 16; off > 0; off >>= 1)
            se += __shfl_xor_sync(0xffffffffu, se, off);
        out[b * 32 + tid] = v - mx - logf(se);
    }
}

// ---------------- launch ----------------
extern "C" void kernel_launch(void* const* d_in, const int* in_sizes, int n_in,
                              void* d_out, int out_size)
{
    const int*   queries = (const int*)  d_in[0];
    const float* emb     = (const float*)d_in[1];
    const float* Wih0f = (const float*)d_in[2],  *Whh0f = (const float*)d_in[3];
    const float* bih0f = (const float*)d_in[4],  *bhh0f = (const float*)d_in[5];
    const float* Wih0b = (const float*)d_in[6],  *Whh0b = (const float*)d_in[7];
    const float* bih0b = (const float*)d_in[8],  *bhh0b = (const float*)d_in[9];
    const float* Wih1f = (const float*)d_in[10], *Whh1f = (const float*)d_in[11];
    const float* bih1f = (const float*)d_in[12], *bhh1f = (const float*)d_in[13];
    const float* Wih1b = (const float*)d_in[14], *Whh1b = (const float*)d_in[15];
    const float* bih1b = (const float*)d_in[16], *bhh1b = (const float*)d_in[17];
    const float* W_out = (const float*)d_in[18], *b_out = (const float*)d_in[19];

    init_states<<<512, 256>>>();
    gather_embed<<<Tt*Bb, 64>>>(queries, emb);

    dim3 tg(G4H/32, Hh/32);
    transposeWP<<<tg, dim3(32,8)>>>(Whh0f, 0);
    transposeWP<<<tg, dim3(32,8)>>>(Whh0b, 1);
    transposeWP<<<tg, dim3(32,8)>>>(Whh1f, 2);
    transposeWP<<<tg, dim3(32,8)>>>(Whh1b, 3);

    dim3 gg(G4H/128, (Tt*Bb)/128);   // (16, 64)
    sgemm_tf32<<<gg, 256>>>(0, 0, Ee,   Wih0f, bih0f, bhh0f);
    sgemm_tf32<<<gg, 256>>>(0, 1, Ee,   Wih0b, bih0b, bhh0b);

    lstm_persist<<<128, 256>>>(0);

    sgemm_tf32<<<gg, 256>>>(1, 2, 2*Hh, Wih1f, bih1f, bhh1f);
    sgemm_tf32<<<gg, 256>>>(1, 3, 2*Hh, Wih1b, bih1b, bhh1b);

    lstm_persist<<<128, 256>>>(1);

    logits_kernel<<<Bb, 256>>>(W_out, b_out, (float*)d_out);
}

// round 9
// speedup vs baseline: 1.0750x; 1.0750x over previous
#include <cuda_runtime.h>
#include <stdint.h>

#define Bb   64
#define Tt   128
#define Ee   256
#define Hh   512
#define G4H  2048
#define GSZ  (Tt*Bb*G4H)   /* 16,777,216 floats per gate buffer */
#define PSTRIDE 34         /* padded col stride of pslab */
#define PADM 132           /* padded m/n stride for ff tf32 smem tiles */

typedef unsigned long long u64;

// ---------------- scratch (__device__ globals: allocation-free) ----------------
__device__ float g_x0[Tt*Bb*Ee];                 // embedded inputs  [T*B, E]
__device__ float g_x1[Tt*Bb*2*Hh];               // layer-0 outputs  [T*B, 2H]
__device__ float g_G[(size_t)4*GSZ];             // gate pre-acts: G0f,G0b,G1f,G1b
__device__ float g_WT[4][Hh*G4H];                // Whh transposed [k][j] per sequence
__device__ float g_hT[4][Hh*Bb];                 // h transposed [k][b] per sequence
__device__ float g_c[4][Bb*Hh];                  // c state per sequence
__device__ unsigned g_bar[2][2];                 // [layer][dir] barrier counters

// ---------------- helpers ----------------
__device__ __forceinline__ void fma2(u64 &c, u64 a, u64 b) {
    asm("fma.rn.f32x2 %0, %1, %2, %0;" : "+l"(c) : "l"(a), "l"(b));
}
__device__ __forceinline__ u64 dup2(float v) {
    u64 r; asm("mov.b64 %0, {%1, %1};" : "=l"(r) : "f"(v)); return r;
}
__device__ __forceinline__ float2 unpack2(u64 v) {
    float2 r; asm("mov.b64 {%0,%1}, %2;" : "=f"(r.x), "=f"(r.y) : "l"(v)); return r;
}
__device__ __forceinline__ float sigm(float x) { return 1.f / (1.f + __expf(-x)); }
__device__ __forceinline__ float tanh_fast(float x) {
    float xc = fminf(fmaxf(x, -15.f), 15.f);
    float e = __expf(-2.f * xc);
    return __fdividef(1.f - e, 1.f + e);
}
__device__ __forceinline__ uint32_t f2tf32(float x) {
    uint32_t r; asm("cvt.rna.tf32.f32 %0, %1;" : "=r"(r) : "f"(x)); return r;
}
__device__ __forceinline__ void mma_tf32(float* c,
        uint32_t a0, uint32_t a1, uint32_t a2, uint32_t a3,
        uint32_t b0, uint32_t b1) {
    asm volatile("mma.sync.aligned.m16n8k8.row.col.f32.tf32.tf32.f32 "
        "{%0,%1,%2,%3}, {%4,%5,%6,%7}, {%8,%9}, {%0,%1,%2,%3};"
        : "+f"(c[0]), "+f"(c[1]), "+f"(c[2]), "+f"(c[3])
        : "r"(a0), "r"(a1), "r"(a2), "r"(a3), "r"(b0), "r"(b1));
}

// ---------------- init: zero h, c, barriers ----------------
__global__ void init_states() {
    int i = blockIdx.x * blockDim.x + threadIdx.x;
    if (i < 4*Hh*Bb) ((float*)g_hT)[i] = 0.f;
    if (i < 4*Bb*Hh) ((float*)g_c)[i] = 0.f;
    if (i < 4)       ((unsigned*)g_bar)[i] = 0u;
}

// ---------------- Whh transpose: g_WT[seq][k*2048+j] = Whh[j*512+k] ----------------
__global__ void transposeW(const float* __restrict__ W, int seq) {
    __shared__ float tile[32][33];
    int j0 = blockIdx.x * 32, k0 = blockIdx.y * 32;
    int tx = threadIdx.x, ty = threadIdx.y;
#pragma unroll
    for (int r = 0; r < 32; r += 8)
        tile[ty + r][tx] = W[(size_t)(j0 + ty + r) * Hh + k0 + tx];
    __syncthreads();
    float* WT = g_WT[seq];
#pragma unroll
    for (int r = 0; r < 32; r += 8)
        WT[(size_t)(k0 + ty + r) * G4H + j0 + tx] = tile[tx][ty + r];
}

// ---------------- embedding gather ----------------
__global__ void gather_embed(const int* __restrict__ q, const float* __restrict__ emb) {
    int r = blockIdx.x;              // r = t*B + b
    int b = r & (Bb - 1);
    int t = r >> 6;
    int qi = q[b * Tt + t];
    const float4* src = (const float4*)(emb + (size_t)qi * Ee);
    float4* dst = (float4*)(g_x0 + (size_t)r * Ee);
    dst[threadIdx.x] = src[threadIdx.x];
}

// ---------------- feedforward GEMM via tf32 mma (unchanged from R7) ----------------
__global__ __launch_bounds__(256) void sgemm_tf32(int asel, int gsel, int K,
        const float* __restrict__ W,
        const float* __restrict__ b1, const float* __restrict__ b2)
{
    const float* __restrict__ A = asel ? g_x1 : g_x0;
    float* __restrict__ C = g_G + (size_t)gsel * GSZ;

    __shared__ uint32_t As[2][16*PADM];
    __shared__ uint32_t Bs[2][16*PADM];

    const int tid = threadIdx.x;
    const int m0 = blockIdx.y * 128, n0 = blockIdx.x * 128;
    const int w = tid >> 5, lane = tid & 31;
    const int gid = lane >> 2, tig = lane & 3;
    const int wm = (w & 1) * 64;
    const int wn = (w >> 1) * 32;

    float acc[4][4][4];
#pragma unroll
    for (int mt = 0; mt < 4; mt++)
#pragma unroll
        for (int nt = 0; nt < 4; nt++)
#pragma unroll
            for (int i = 0; i < 4; i++) acc[mt][nt][i] = 0.f;

    const int sr = tid >> 2;
    const int sc = (tid & 3) * 4;
    const float* Ar0 = A + (size_t)(m0 + sr) * K + sc;
    const float* Ar1 = A + (size_t)(m0 + sr + 64) * K + sc;
    const float* Wr0 = W + (size_t)(n0 + sr) * K + sc;
    const float* Wr1 = W + (size_t)(n0 + sr + 64) * K + sc;

#define STS_T(bsel, va0, va1, vb0, vb1) { \
    As[bsel][(sc+0)*PADM + sr]    = f2tf32(va0.x); \
    As[bsel][(sc+1)*PADM + sr]    = f2tf32(va0.y); \
    As[bsel][(sc+2)*PADM + sr]    = f2tf32(va0.z); \
    As[bsel][(sc+3)*PADM + sr]    = f2tf32(va0.w); \
    As[bsel][(sc+0)*PADM + sr+64] = f2tf32(va1.x); \
    As[bsel][(sc+1)*PADM + sr+64] = f2tf32(va1.y); \
    As[bsel][(sc+2)*PADM + sr+64] = f2tf32(va1.z); \
    As[bsel][(sc+3)*PADM + sr+64] = f2tf32(va1.w); \
    Bs[bsel][(sc+0)*PADM + sr]    = f2tf32(vb0.x); \
    Bs[bsel][(sc+1)*PADM + sr]    = f2tf32(vb0.y); \
    Bs[bsel][(sc+2)*PADM + sr]    = f2tf32(vb0.z); \
    Bs[bsel][(sc+3)*PADM + sr]    = f2tf32(vb0.w); \
    Bs[bsel][(sc+0)*PADM + sr+64] = f2tf32(vb1.x); \
    Bs[bsel][(sc+1)*PADM + sr+64] = f2tf32(vb1.y); \
    Bs[bsel][(sc+2)*PADM + sr+64] = f2tf32(vb1.z); \
    Bs[bsel][(sc+3)*PADM + sr+64] = f2tf32(vb1.w); }

    {
        float4 va0 = *(const float4*)Ar0;
        float4 va1 = *(const float4*)Ar1;
        float4 vb0 = *(const float4*)Wr0;
        float4 vb1 = *(const float4*)Wr1;
        STS_T(0, va0, va1, vb0, vb1);
    }
    __syncthreads();

    int buf = 0;
    for (int kt = 0; kt < K; kt += 16) {
        float4 va0, va1, vb0, vb1;
        bool more = (kt + 16 < K);
        if (more) {
            va0 = *(const float4*)(Ar0 + kt + 16);
            va1 = *(const float4*)(Ar1 + kt + 16);
            vb0 = *(const float4*)(Wr0 + kt + 16);
            vb1 = *(const float4*)(Wr1 + kt + 16);
        }
#pragma unroll
        for (int kk = 0; kk < 16; kk += 8) {
            uint32_t af[4][4], bf[4][2];
            const uint32_t* a_lo = &As[buf][(kk + tig) * PADM + wm + gid];
            const uint32_t* a_hi = &As[buf][(kk + tig + 4) * PADM + wm + gid];
            const uint32_t* b_lo = &Bs[buf][(kk + tig) * PADM + wn + gid];
            const uint32_t* b_hi = &Bs[buf][(kk + tig + 4) * PADM + wn + gid];
#pragma unroll
            for (int mt = 0; mt < 4; mt++) {
                af[mt][0] = a_lo[mt*16];
                af[mt][1] = a_lo[mt*16 + 8];
                af[mt][2] = a_hi[mt*16];
                af[mt][3] = a_hi[mt*16 + 8];
            }
#pragma unroll
            for (int nt = 0; nt < 4; nt++) {
                bf[nt][0] = b_lo[nt*8];
                bf[nt][1] = b_hi[nt*8];
            }
#pragma unroll
            for (int mt = 0; mt < 4; mt++)
#pragma unroll
                for (int nt = 0; nt < 4; nt++)
                    mma_tf32(acc[mt][nt], af[mt][0], af[mt][1], af[mt][2], af[mt][3],
                             bf[nt][0], bf[nt][1]);
        }
        if (more) {
            STS_T(buf ^ 1, va0, va1, vb0, vb1);
            __syncthreads();
            buf ^= 1;
        }
    }
#undef STS_T

#pragma unroll
    for (int nt = 0; nt < 4; nt++) {
        int gn = n0 + wn + nt * 8 + 2 * tig;
        float bs0 = b1[gn]   + b2[gn];
        float bs1 = b1[gn+1] + b2[gn+1];
#pragma unroll
        for (int mt = 0; mt < 4; mt++) {
            int gm = m0 + wm + mt * 16 + gid;
            float* c0 = C + (size_t)gm * G4H + gn;
            float* c1 = C + (size_t)(gm + 8) * G4H + gn;
            c0[0] = acc[mt][nt][0] + bs0;
            c0[1] = acc[mt][nt][1] + bs1;
            c1[0] = acc[mt][nt][2] + bs0;
            c1[1] = acc[mt][nt][3] + bs1;
        }
    }
}

// ---------------- per-direction software barrier (release/acquire) ----------------
__device__ __forceinline__ void dirbar(unsigned* ctr, unsigned target) {
    __syncthreads();
    if (threadIdx.x == 0) {
        asm volatile("red.release.gpu.global.add.u32 [%0], %1;"
                     :: "l"(ctr), "r"(1u) : "memory");
        unsigned v;
        do {
            asm volatile("ld.acquire.gpu.global.u32 %0, [%1];"
                         : "=r"(v) : "l"(ctr) : "memory");
            if (v >= target) break;
            __nanosleep(32);
        } while (true);
    }
    __syncthreads();
}

// ---------------- persistent recurrence: one layer, both dirs, 128 steps ----------------
// R7 FMA inner loop (R=2.0 B/fma2), 3-buffer A pipeline, fast-tanh + float2 elementwise.
#define LOAD_A(buf, kb) { \
    _Pragma("unroll") for (int kk = 0; kk < 4; kk++) { \
        const float4* p = (const float4*)(hT + ((kb) + kk) * Bb + m0); \
        buf[kk][0] = __ldcg(p); buf[kk][1] = __ldcg(p + 1); } }

#define COMPUTE(buf, kb) { \
    _Pragma("unroll") for (int kk = 0; kk < 4; kk++) { \
        const ulonglong2* bp = (const ulonglong2*)(WT + (size_t)((kb) + kk) * G4H + cb); \
        ulonglong2 b0 = bp[0], b1 = bp[1]; \
        u64 br0 = b0.x, br1 = b0.y, br2 = b1.x, br3 = b1.y; \
        float av[8] = { buf[kk][0].x, buf[kk][0].y, buf[kk][0].z, buf[kk][0].w, \
                        buf[kk][1].x, buf[kk][1].y, buf[kk][1].z, buf[kk][1].w }; \
        _Pragma("unroll") for (int mi = 0; mi < 8; mi++) { \
            u64 ad = dup2(av[mi]); \
            fma2(acc[mi][0], ad, br0); fma2(acc[mi][1], ad, br1); \
            fma2(acc[mi][2], ad, br2); fma2(acc[mi][3], ad, br3); } } }

__global__ __launch_bounds__(256, 1) void lstm_persist(int layer)
{
    __shared__ float pslab[4 * Bb * PSTRIDE];    // 34,816 B static

    const int tid = threadIdx.x;
    const int dir = blockIdx.x >> 6;
    const int sub = blockIdx.x & 63;
    const int seq = layer * 2 + dir;
    const int w   = tid >> 5;
    const int lane = tid & 31;
    const int lane_m = lane >> 2;                // 0..7  -> m0 = lane_m*8
    const int lane_c = lane & 3;                 // 0..3  -> gate g
    const int m0 = lane_m * 8;
    const int cb = lane_c * Hh + sub * 8;        // global gate-col base (8 cols)
    const int ks = w * 64;
    const int wslab = w & 3;                     // slab index shared by w and w+4

    const float* __restrict__ WT = g_WT[seq];
    float* __restrict__ hT = g_hT[seq];
    float* __restrict__ cs = g_c[seq];
    const float* __restrict__ Gseq = g_G + (size_t)seq * GSZ;
    unsigned* bar = &g_bar[layer][dir];

    // elementwise mapping: thread -> (m, u-pair)
    const int ew_m = tid >> 2;                   // 0..63
    const int ew_up = (tid & 3) * 2;             // 0,2,4,6

    for (int s = 0; s < Tt; s++) {
        const int t = dir ? (Tt - 1 - s) : s;

        // ---------- prefetch gate pre-acts (DRAM) as float2 pairs ----------
        const float* Gt = Gseq + (size_t)t * Bb * G4H;
        float2 gpre[4];
#pragma unroll
        for (int g = 0; g < 4; g++)
            gpre[g] = __ldcg((const float2*)&Gt[(size_t)ew_m * G4H + g * Hh + sub * 8 + ew_up]);

        // ---------- per-warp partial GEMM over its K slice (regs only) ----------
        u64 acc[8][4];
#pragma unroll
        for (int mi = 0; mi < 8; mi++) { acc[mi][0]=0; acc[mi][1]=0; acc[mi][2]=0; acc[mi][3]=0; }

        float4 Ab[3][4][2];
        LOAD_A(Ab[0], ks);
        LOAD_A(Ab[1], ks + 4);
#pragma unroll
        for (int q = 0; q < 16; q++) {
            if (q + 2 < 16) LOAD_A(Ab[(q + 2) % 3], ks + (q + 2) * 4);
            COMPUTE(Ab[q % 3], ks + q * 4);
        }

        // ---------- round 1: warps 0-3 write slabs ----------
        if (w < 4) {
#pragma unroll
            for (int mi = 0; mi < 8; mi++) {
                float* prow = &pslab[(wslab * Bb + m0 + mi) * PSTRIDE + lane_c * 8];
                *(u64*)(prow)     = acc[mi][0];
                *(u64*)(prow + 2) = acc[mi][1];
                *(u64*)(prow + 4) = acc[mi][2];
                *(u64*)(prow + 6) = acc[mi][3];
            }
        }
        __syncthreads();
        // ---------- round 2: warps 4-7 accumulate into partner slab ----------
        if (w >= 4) {
#pragma unroll
            for (int mi = 0; mi < 8; mi++) {
                float* prow = &pslab[(wslab * Bb + m0 + mi) * PSTRIDE + lane_c * 8];
#pragma unroll
                for (int c = 0; c < 4; c++) {
                    float2 cur = *(float2*)(prow + 2*c);
                    float2 ad  = unpack2(acc[mi][c]);
                    cur.x += ad.x; cur.y += ad.y;
                    *(float2*)(prow + 2*c) = cur;
                }
            }
        }
        __syncthreads();

        // ---------- K-reduce (4 slabs) + prefetched input proj + LSTM elementwise ----------
        {
            float2 pre[4];
#pragma unroll
            for (int g = 0; g < 4; g++) {
                float2 v = gpre[g];
#pragma unroll
                for (int ww = 0; ww < 4; ww++) {
                    float2 p = *(const float2*)&pslab[(ww * Bb + ew_m) * PSTRIDE + g * 8 + ew_up];
                    v.x += p.x; v.y += p.y;
                }
                pre[g] = v;
            }
            int ci = ew_m * Hh + sub * 8 + ew_up;
            float2 c2 = *(float2*)&cs[ci];

            float i0 = sigm(pre[0].x), i1 = sigm(pre[0].y);
            float f0 = sigm(pre[1].x), f1 = sigm(pre[1].y);
            float gg0 = tanh_fast(pre[2].x), gg1 = tanh_fast(pre[2].y);
            float o0 = sigm(pre[3].x), o1 = sigm(pre[3].y);

            float cn0 = f0 * c2.x + i0 * gg0;
            float cn1 = f1 * c2.y + i1 * gg1;
            float hn0 = o0 * tanh_fast(cn0);
            float hn1 = o1 * tanh_fast(cn1);

            *(float2*)&cs[ci] = make_float2(cn0, cn1);
            hT[(sub * 8 + ew_up) * Bb + ew_m]     = hn0;
            hT[(sub * 8 + ew_up + 1) * Bb + ew_m] = hn1;
            if (layer == 0)
                *(float2*)&g_x1[((size_t)t * Bb + ew_m) * (2*Hh) + dir * Hh + sub * 8 + ew_up]
                    = make_float2(hn0, hn1);
        }

        dirbar(bar, 64u * (s + 1));   // single barrier: h complete for next step
    }
}

// ---------------- output head: logits + log_softmax ----------------
__global__ void logits_kernel(const float* __restrict__ Wout,
                              const float* __restrict__ bout,
                              float* __restrict__ out)
{
    __shared__ float h[2048];
    __shared__ float red[256];
    __shared__ float lg[32];
    int b = blockIdx.x, tid = threadIdx.x;
    for (int i = tid; i < 2048; i += 256) {
        int seg = i >> 9, k = i & 511;           // order: l0f, l0b, l1f, l1b
        h[i] = g_hT[seg][k * Bb + b];
    }
    __syncthreads();
    int e = tid >> 3, part = tid & 7;
    const float4* wrow = (const float4*)(Wout + (size_t)e * 2048 + part * 256);
    const float4* hp   = (const float4*)(h + part * 256);
    float sum = 0.f;
#pragma unroll 8
    for (int i = 0; i < 64; i++) {
        float4 wv = wrow[i], hv = hp[i];
        sum += wv.x*hv.x + wv.y*hv.y + wv.z*hv.z + wv.w*hv.w;
    }
    red[tid] = sum;
    __syncthreads();
    if (part == 0) {
        float sacc = 0.f;
#pragma unroll
        for (int i = 0; i < 8; i++) sacc += red[tid + i];
        lg[e] = sacc + bout[e];
    }
    __syncthreads();
    if (tid < 32) {
        float v = lg[tid];
        float mx = v;
#pragma unroll
        for (int off = 16; off > 0; off >>= 1)
            mx = fmaxf(mx, __shfl_xor_sync(0xffffffffu, mx, off));
        float ex = __expf(v - mx);
        float se = ex;
#pragma unroll
        for (int off = 16; off > 0; off >>= 1)
            se += __shfl_xor_sync(0xffffffffu, se, off);
        out[b * 32 + tid] = v - mx - logf(se);
    }
}

// ---------------- launch ----------------
extern "C" void kernel_launch(void* const* d_in, const int* in_sizes, int n_in,
                              void* d_out, int out_size)
{
    const int*   queries = (const int*)  d_in[0];
    const float* emb     = (const float*)d_in[1];
    const float* Wih0f = (const float*)d_in[2],  *Whh0f = (const float*)d_in[3];
    const float* bih0f = (const float*)d_in[4],  *bhh0f = (const float*)d_in[5];
    const float* Wih0b = (const float*)d_in[6],  *Whh0b = (const float*)d_in[7];
    const float* bih0b = (const float*)d_in[8],  *bhh0b = (const float*)d_in[9];
    const float* Wih1f = (const float*)d_in[10], *Whh1f = (const float*)d_in[11];
    const float* bih1f = (const float*)d_in[12], *bhh1f = (const float*)d_in[13];
    const float* Wih1b = (const float*)d_in[14], *Whh1b = (const float*)d_in[15];
    const float* bih1b = (const float*)d_in[16], *bhh1b = (const float*)d_in[17];
    const float* W_out = (const float*)d_in[18], *b_out = (const float*)d_in[19];

    init_states<<<512, 256>>>();
    gather_embed<<<Tt*Bb, 64>>>(queries, emb);

    dim3 tg(G4H/32, Hh/32);
    transposeW<<<tg, dim3(32,8)>>>(Whh0f, 0);
    transposeW<<<tg, dim3(32,8)>>>(Whh0b, 1);
    transposeW<<<tg, dim3(32,8)>>>(Whh1f, 2);
    transposeW<<<tg, dim3(32,8)>>>(Whh1b, 3);

    dim3 gg(G4H/128, (Tt*Bb)/128);   // (16, 64)
    sgemm_tf32<<<gg, 256>>>(0, 0, Ee,   Wih0f, bih0f, bhh0f);
    sgemm_tf32<<<gg, 256>>>(0, 1, Ee,   Wih0b, bih0b, bhh0b);

    lstm_persist<<<128, 256>>>(0);

    sgemm_tf32<<<gg, 256>>>(1, 2, 2*Hh, Wih1f, bih1f, bhh1f);
    sgemm_tf32<<<gg, 256>>>(1, 3, 2*Hh, Wih1b, bih1b, bhh1b);

    lstm_persist<<<128, 256>>>(1);

    logits_kernel<<<Bb, 256>>>(W_out, b_out, (float*)d_out);
}